// round 11
// baseline (speedup 1.0000x reference)
#include <cuda_runtime.h>
#include <cuda_fp16.h>
#include <cstdint>

#define N_SEL   192
#define N_PTS   2048
#define C_IN    256
#define C_OUT   256
#define N_TILES 8

#define BM 64
#define BN 256
#define BK 64
#define NSLABS (C_IN / BK)   // 4
#define THREADS 256

#define ROWA  528            // A row: 256 fp16 = 512B + 16 pad (33×16B units, %8=1 -> conflict-free)
#define ROWB  144            // B row: 64 fp16 = 128B + 16 pad  (9×16B units,  %8=1 -> conflict-free)

// dynamic smem layout
#define SM_BIAS  0                         // 256 f32 = 1024 B
#define SM_A     1024                      // 64 rows x 528 B (full K, resident)
#define SM_B     (SM_A + BM * ROWA)        // 34816; 2 stages x 256 rows x 144 B
#define B_STG    (BN * ROWB)               // 36864
#define SM_TOTAL (SM_B + 2 * B_STG)        // 108544

// gathered, transposed fp16 weights: [n_sel][N=C_OUT][K=C_IN]
__device__ __half g_wt[(size_t)N_SEL * C_OUT * C_IN];

__device__ __forceinline__ uint32_t smem_u32(const void* p) {
    uint32_t a;
    asm("{ .reg .u64 t; cvta.to.shared.u64 t, %1; cvt.u32.u64 %0, t; }" : "=r"(a) : "l"(p));
    return a;
}
__device__ __forceinline__ void cp16(uint32_t dst, const void* src) {
    asm volatile("cp.async.cg.shared.global [%0], [%1], 16;" :: "r"(dst), "l"(src));
}
__device__ __forceinline__ uint32_t pack_h2(float a, float b) {
    uint32_t r;
    asm("cvt.rn.f16x2.f32 %0, %2, %1;" : "=r"(r) : "f"(a), "f"(b));
    return r;
}
__device__ __forceinline__ void ldmx4(uint32_t addr, uint32_t& r0, uint32_t& r1,
                                      uint32_t& r2, uint32_t& r3) {
    asm volatile("ldmatrix.sync.aligned.m8n8.x4.shared.b16 {%0,%1,%2,%3}, [%4];"
                 : "=r"(r0), "=r"(r1), "=r"(r2), "=r"(r3) : "r"(addr));
}
__device__ __forceinline__ void mma_f16(float* c, const uint32_t* a, const uint32_t* b) {
    asm volatile("mma.sync.aligned.m16n8k16.row.col.f32.f16.f16.f32 "
                 "{%0,%1,%2,%3}, {%4,%5,%6,%7}, {%8,%9}, {%0,%1,%2,%3};"
                 : "+f"(c[0]), "+f"(c[1]), "+f"(c[2]), "+f"(c[3])
                 : "r"(a[0]), "r"(a[1]), "r"(a[2]), "r"(a[3]), "r"(b[0]), "r"(b[1]));
}

// ---------------- kernel 1: gather + transpose + fp16 convert of W ----------------
__global__ void wt_prep_kernel(const float* __restrict__ weight,
                               const int* __restrict__ indices,
                               const int* __restrict__ t_ptr) {
    const int n = blockIdx.z;
    const int t = (t_ptr != nullptr) ? *t_ptr : 3;
    const int idx = indices[n];
    const float* W = weight + (((size_t)idx * N_TILES + t) * C_IN) * C_OUT; // [K][N]

    __shared__ float tile[32][33];
    const int tx = threadIdx.x;   // 0..31
    const int ty = threadIdx.y;   // 0..7
    const int kt = blockIdx.y * 32;
    const int nt = blockIdx.x * 32;

    #pragma unroll
    for (int j = 0; j < 4; j++) {
        const int k = kt + ty + j * 8;
        tile[ty + j * 8][tx] = W[(size_t)k * C_OUT + nt + tx];
    }
    __syncthreads();

    __half* o = g_wt + (size_t)n * C_OUT * C_IN;
    #pragma unroll
    for (int j = 0; j < 4; j++) {
        const int nn = nt + ty + j * 8;
        o[(size_t)nn * C_IN + kt + tx] = __float2half_rn(tile[tx][ty + j * 8]);
    }
}

// ---------------- kernel 2: A-resident fp16 mma.sync GEMM ----------------
__global__ __launch_bounds__(THREADS, 2)
void gemm_f16_kernel(const float* __restrict__ x,
                     const float* __restrict__ bias,
                     const int* __restrict__ indices,
                     const int* __restrict__ t_ptr,
                     float* __restrict__ out) {
    extern __shared__ __align__(16) unsigned char smem[];
    const uint32_t sa = smem_u32(smem);

    const int tid  = threadIdx.x;
    const int lane = tid & 31;
    const int wid  = tid >> 5;          // 0..7

    const int n_sel = blockIdx.y;
    const int m0    = blockIdx.x * BM;
    const int t   = (t_ptr != nullptr) ? *t_ptr : 3;
    const int idx = indices[n_sel];

    const float* A = x + (size_t)n_sel * N_PTS * C_IN + (size_t)m0 * C_IN;
    const __half* Wn = g_wt + (size_t)n_sel * C_OUT * C_IN;

    // B cp.async: one 64-k slab = 256 rows x 8 chunks of 16B -> 8 per thread
    auto issue_B = [&](int s) {
        const uint32_t base = sa + SM_B + (uint32_t)(s & 1) * B_STG;
        const int k0 = s * BK;
        #pragma unroll
        for (int i = 0; i < 8; i++) {
            const int c = tid + i * THREADS;
            const int r = c >> 3, seg = c & 7;
            cp16(base + (uint32_t)(r * ROWB + seg * 16),
                 Wn + (size_t)r * C_IN + k0 + seg * 8);
        }
        asm volatile("cp.async.commit_group;" ::: "memory");
    };

    issue_B(0);   // B slab 0 in flight while we build A

    // ---- one-time: load + convert full A tile (64 x 256) into resident smem ----
    {
        const int r  = tid >> 2;            // row 0..63
        const int c0 = (tid & 3) * 64;      // col start (floats)
        const float* src = A + (size_t)r * C_IN + c0;
        #pragma unroll
        for (int j = 0; j < 8; j++) {
            const float4 f0 = *reinterpret_cast<const float4*>(src + j * 8);
            const float4 f1 = *reinterpret_cast<const float4*>(src + j * 8 + 4);
            uint4 v;
            v.x = pack_h2(f0.x, f0.y);
            v.y = pack_h2(f0.z, f0.w);
            v.z = pack_h2(f1.x, f1.y);
            v.w = pack_h2(f1.z, f1.w);
            *reinterpret_cast<uint4*>(smem + SM_A + r * ROWA + c0 * 2 + j * 16) = v;
        }
    }

    // bias -> smem
    float* bs = (float*)(smem + SM_BIAS);
    if (tid < C_OUT) bs[tid] = bias[((size_t)idx * N_TILES + t) * C_OUT + tid];

    // warp tiling: 2 m-warps x 4 n-warps; warp tile 32x64
    const int m_off = (wid >> 2) * 32;
    const int n_off = (wid & 3) * 64;

    float acc[2][8][4];
    #pragma unroll
    for (int i = 0; i < 2; i++)
        #pragma unroll
        for (int j = 0; j < 8; j++)
            #pragma unroll
            for (int q = 0; q < 4; q++)
                acc[i][j][q] = 0.0f;

    for (int s = 0; s < NSLABS; s++) {
        asm volatile("cp.async.wait_group 0;" ::: "memory");   // B(s) landed
        __syncthreads();   // publishes A (s==0) + B stage s&1; frees stage (s-1)&1

        if (s + 1 < NSLABS) issue_B(s + 1);   // overlaps with compute below

        const uint32_t aB = sa + SM_A;
        const uint32_t bB = sa + SM_B + (uint32_t)((s & 1) * B_STG);
        const int kbase = s * BK;

        #pragma unroll
        for (int ks = 0; ks < BK; ks += 16) {
            uint32_t bf[8][2];
            #pragma unroll
            for (int p = 0; p < 4; p++) {
                const int quad = lane >> 3;
                const int rowB = n_off + p * 16 + ((quad >> 1) & 1) * 8 + (lane & 7);
                const int colB = ks + (quad & 1) * 8;
                ldmx4(bB + (uint32_t)(rowB * ROWB + colB * 2),
                      bf[2 * p][0], bf[2 * p][1], bf[2 * p + 1][0], bf[2 * p + 1][1]);
            }
            #pragma unroll
            for (int mf = 0; mf < 2; mf++) {
                const int rowA = m_off + mf * 16 + (lane & 15);
                const int colA = kbase + ks + ((lane >> 4) & 1) * 8;
                uint32_t af[4];
                ldmx4(aB + (uint32_t)(rowA * ROWA + colA * 2), af[0], af[1], af[2], af[3]);
                #pragma unroll
                for (int nf = 0; nf < 8; nf++)
                    mma_f16(acc[mf][nf], af, bf[nf]);
            }
        }
        // stage safety: issue_B(s+1) (stage (s+1)&1) happens after the barrier
        // that proves all warps finished reading that stage during slab s-1.
    }

    // ---- epilogue: + bias, float2 stores ----
    float* Out = out + (size_t)n_sel * N_PTS * C_OUT + (size_t)m0 * C_OUT;
    const int r4 = lane >> 2;
    const int c2 = (lane & 3) * 2;
    #pragma unroll
    for (int mf = 0; mf < 2; mf++) {
        #pragma unroll
        for (int nf = 0; nf < 8; nf++) {
            const int col = n_off + nf * 8 + c2;
            const float bx = bs[col], by = bs[col + 1];
            const int row0 = m_off + mf * 16 + r4;
            float2 o0, o1;
            o0.x = acc[mf][nf][0] + bx; o0.y = acc[mf][nf][1] + by;
            o1.x = acc[mf][nf][2] + bx; o1.y = acc[mf][nf][3] + by;
            *reinterpret_cast<float2*>(Out + (size_t)row0 * C_OUT + col) = o0;
            *reinterpret_cast<float2*>(Out + (size_t)(row0 + 8) * C_OUT + col) = o1;
        }
    }
}

extern "C" void kernel_launch(void* const* d_in, const int* in_sizes, int n_in,
                              void* d_out, int out_size) {
    const float* x       = (const float*)d_in[0];
    const float* weight  = (const float*)d_in[1];
    const float* bias    = (const float*)d_in[2];
    const int*   indices = (const int*)d_in[3];
    const int*   t_ptr   = (n_in > 4) ? (const int*)d_in[4] : nullptr;
    float*       out     = (float*)d_out;

    {
        dim3 grid(C_OUT / 32, C_IN / 32, N_SEL);
        dim3 block(32, 8);
        wt_prep_kernel<<<grid, block>>>(weight, indices, t_ptr);
    }
    {
        cudaFuncSetAttribute(gemm_f16_kernel,
                             cudaFuncAttributeMaxDynamicSharedMemorySize, SM_TOTAL);
        dim3 grid(N_PTS / BM, N_SEL);   // (32, 192); m fastest -> same-W adjacency
        dim3 block(THREADS);
        gemm_f16_kernel<<<grid, block, SM_TOTAL>>>(x, bias, indices, t_ptr, out);
    }
}

// round 12
// speedup vs baseline: 1.1337x; 1.1337x over previous
#include <cuda_runtime.h>
#include <cuda_fp16.h>
#include <cstdint>

#define N_SEL   192
#define N_PTS   2048
#define C_IN    256
#define C_OUT   256
#define N_TILES 8

#define BM 128
#define BN 256
#define BK 32
#define NSLABS 8            // k-slabs
#define NMT    8            // m-tiles per CTA (m-half = 8 * 128)
#define THREADS 512

#define ROWB  80            // tile row: 32 fp16 (64B) + 16 pad

// dynamic smem
#define SM_BIAS  0                          // 256 f32
#define SM_A     1024                       // 2 stages x 128 x 80
#define A_STG    (BM * ROWB)                // 10240
#define SM_W     (SM_A + 2 * A_STG)         // 21504; 8 k-slab tiles x 256 x 80
#define W_STG    (BN * ROWB)                // 20480
#define SM_TOTAL (SM_W + NSLABS * W_STG)    // 185344

__device__ __half g_wt[(size_t)N_SEL * C_OUT * C_IN];   // [n_sel][N][K]

__device__ __forceinline__ uint32_t smem_u32(const void* p) {
    uint32_t a;
    asm("{ .reg .u64 t; cvta.to.shared.u64 t, %1; cvt.u32.u64 %0, t; }" : "=r"(a) : "l"(p));
    return a;
}
__device__ __forceinline__ void cp16(uint32_t dst, const void* src) {
    asm volatile("cp.async.cg.shared.global [%0], [%1], 16;" :: "r"(dst), "l"(src));
}
__device__ __forceinline__ uint32_t pack_h2(float a, float b) {
    uint32_t r;
    asm("cvt.rn.f16x2.f32 %0, %2, %1;" : "=r"(r) : "f"(a), "f"(b));
    return r;
}
__device__ __forceinline__ void ldmx4(uint32_t addr, uint32_t& r0, uint32_t& r1,
                                      uint32_t& r2, uint32_t& r3) {
    asm volatile("ldmatrix.sync.aligned.m8n8.x4.shared.b16 {%0,%1,%2,%3}, [%4];"
                 : "=r"(r0), "=r"(r1), "=r"(r2), "=r"(r3) : "r"(addr));
}
__device__ __forceinline__ void mma_f16(float* c, const uint32_t* a, const uint32_t* b) {
    asm volatile("mma.sync.aligned.m16n8k16.row.col.f32.f16.f16.f32 "
                 "{%0,%1,%2,%3}, {%4,%5,%6,%7}, {%8,%9}, {%0,%1,%2,%3};"
                 : "+f"(c[0]), "+f"(c[1]), "+f"(c[2]), "+f"(c[3])
                 : "r"(a[0]), "r"(a[1]), "r"(a[2]), "r"(a[3]), "r"(b[0]), "r"(b[1]));
}
__device__ __forceinline__ void wait_upto(int n) {
    switch (n) {
    case 0: asm volatile("cp.async.wait_group 0;" ::: "memory"); break;
    case 1: asm volatile("cp.async.wait_group 1;" ::: "memory"); break;
    case 2: asm volatile("cp.async.wait_group 2;" ::: "memory"); break;
    case 3: asm volatile("cp.async.wait_group 3;" ::: "memory"); break;
    case 4: asm volatile("cp.async.wait_group 4;" ::: "memory"); break;
    case 5: asm volatile("cp.async.wait_group 5;" ::: "memory"); break;
    case 6: asm volatile("cp.async.wait_group 6;" ::: "memory"); break;
    default: asm volatile("cp.async.wait_group 7;" ::: "memory"); break;
    }
}

// ---------------- kernel 1: gather + transpose + fp16 convert of W ----------------
__global__ void wt_prep_kernel(const float* __restrict__ weight,
                               const int* __restrict__ indices,
                               const int* __restrict__ t_ptr) {
    const int n = blockIdx.z;
    const int t = (t_ptr != nullptr) ? *t_ptr : 3;
    const int idx = indices[n];
    const float* W = weight + (((size_t)idx * N_TILES + t) * C_IN) * C_OUT;

    __shared__ float tile[32][33];
    const int tx = threadIdx.x, ty = threadIdx.y;
    const int kt = blockIdx.y * 32, nt = blockIdx.x * 32;

    #pragma unroll
    for (int j = 0; j < 4; j++)
        tile[ty + j * 8][tx] = W[(size_t)(kt + ty + j * 8) * C_OUT + nt + tx];
    __syncthreads();

    __half* o = g_wt + (size_t)n * C_OUT * C_IN;
    #pragma unroll
    for (int j = 0; j < 4; j++) {
        const int nn = nt + ty + j * 8;
        o[(size_t)nn * C_IN + kt + tx] = __float2half_rn(tile[tx][ty + j * 8]);
    }
}

// ---------------- kernel 2: W-resident fp16 mma.sync GEMM ----------------
__global__ __launch_bounds__(THREADS, 1)
void gemm_f16_kernel(const float* __restrict__ x,
                     const float* __restrict__ bias,
                     const int* __restrict__ indices,
                     const int* __restrict__ t_ptr,
                     float* __restrict__ out) {
    extern __shared__ __align__(16) unsigned char smem[];
    const uint32_t sa = smem_u32(smem);

    const int tid  = threadIdx.x;
    const int lane = tid & 31;
    const int wid  = tid >> 5;          // 0..15

    const int n_sel = blockIdx.y;
    const int mh    = blockIdx.x;       // m-half 0/1
    const int t   = (t_ptr != nullptr) ? *t_ptr : 3;
    const int idx = indices[n_sel];

    const float* Abase = x + ((size_t)n_sel * N_PTS + (size_t)mh * 1024) * C_IN;
    const __half* Wn = g_wt + (size_t)n_sel * C_OUT * C_IN;

    // ---- issue all W k-slab tiles (8 commit groups) ----
    #pragma unroll
    for (int s = 0; s < NSLABS; s++) {
        const uint32_t base = sa + SM_W + (uint32_t)(s * W_STG);
        #pragma unroll
        for (int i = 0; i < 2; i++) {
            const int c = tid + i * THREADS;     // 0..1023
            const int r = c >> 2, seg = c & 3;
            cp16(base + (uint32_t)(r * ROWB + seg * 16),
                 Wn + (size_t)r * C_IN + s * BK + seg * 8);
        }
        asm volatile("cp.async.commit_group;" ::: "memory");
    }

    // bias -> smem
    float* bs = (float*)(smem + SM_BIAS);
    if (tid < C_OUT) bs[tid] = bias[((size_t)idx * N_TILES + t) * C_OUT + tid];

    // warp tiling: 4 m-warps x 4 n-warps; warp tile 32x64
    const int m_off = (wid >> 2) * 32;
    const int n_off = (wid & 3) * 64;

    // A mapping: 512 thr -> 128 rows x 32 cols (8 floats/thread)
    const int ar = tid >> 2;              // 0..127
    const int ac = (tid & 3) * 8;         // col start (floats)
    const uint32_t aSTS = (uint32_t)(SM_A + ar * ROWB + (tid & 3) * 16);

    float acc[2][8][4];
    #pragma unroll
    for (int i = 0; i < 2; i++)
        #pragma unroll
        for (int j = 0; j < 8; j++)
            #pragma unroll
            for (int q = 0; q < 4; q++)
                acc[i][j][q] = 0.0f;

    // prefetch A for iteration 0 (mt=0, s=0)
    float4 a0, a1;
    {
        const float* src = Abase + (size_t)ar * C_IN + ac;
        a0 = *reinterpret_cast<const float4*>(src);
        a1 = *reinterpret_cast<const float4*>(src + 4);
    }

    float* Out = out + ((size_t)n_sel * N_PTS + (size_t)mh * 1024) * C_OUT;
    const int r4 = lane >> 2;
    const int c2 = (lane & 3) * 2;

    for (int mt = 0; mt < NMT; mt++) {
        #pragma unroll
        for (int s = 0; s < NSLABS; s++) {
            const int it  = mt * NSLABS + s;
            const int stg = it & 1;

            // convert A regs (this slab) -> smem stage
            {
                uint4 v;
                v.x = pack_h2(a0.x, a0.y);
                v.y = pack_h2(a0.z, a0.w);
                v.z = pack_h2(a1.x, a1.y);
                v.w = pack_h2(a1.z, a1.w);
                *reinterpret_cast<uint4*>(smem + aSTS + stg * A_STG) = v;
            }
            // prefetch A regs for next iteration
            if (it + 1 < NMT * NSLABS) {
                const int nit = it + 1;
                const float* src = Abase + (size_t)((nit >> 3) * BM + ar) * C_IN
                                 + (nit & 7) * BK + ac;
                a0 = *reinterpret_cast<const float4*>(src);
                a1 = *reinterpret_cast<const float4*>(src + 4);
            }
            if (mt == 0) wait_upto(7 - s);   // W tile s landed
            __syncthreads();                 // publishes A stage + (mt0) W tile

            const uint32_t aB = sa + SM_A + (uint32_t)(stg * A_STG);
            const uint32_t wB = sa + SM_W + (uint32_t)(s * W_STG);

            #pragma unroll
            for (int ks = 0; ks < BK; ks += 16) {
                uint32_t bf[8][2];
                #pragma unroll
                for (int p = 0; p < 4; p++) {
                    const int quad = lane >> 3;
                    const int rowB = n_off + p * 16 + ((quad >> 1) & 1) * 8 + (lane & 7);
                    const int colB = ks + (quad & 1) * 8;
                    ldmx4(wB + (uint32_t)(rowB * ROWB + colB * 2),
                          bf[2 * p][0], bf[2 * p][1], bf[2 * p + 1][0], bf[2 * p + 1][1]);
                }
                #pragma unroll
                for (int mf = 0; mf < 2; mf++) {
                    const int rowA = m_off + mf * 16 + (lane & 15);
                    const int colA = ks + ((lane >> 4) & 1) * 8;
                    uint32_t af[4];
                    ldmx4(aB + (uint32_t)(rowA * ROWB + colA * 2), af[0], af[1], af[2], af[3]);
                    #pragma unroll
                    for (int nf = 0; nf < 8; nf++)
                        mma_f16(acc[mf][nf], af, bf[nf]);
                }
            }
            // A-stage safety: STS(it+2) executes after barrier(it+1), which is
            // after every warp's compute(it) that read this stage.
        }

        // ---- epilogue for m-tile mt (regs -> gmem, no smem hazards) ----
        float* Om = Out + (size_t)mt * BM * C_OUT;
        #pragma unroll
        for (int mf = 0; mf < 2; mf++) {
            #pragma unroll
            for (int nf = 0; nf < 8; nf++) {
                const int col = n_off + nf * 8 + c2;
                const float bx = bs[col], by = bs[col + 1];
                const int row0 = m_off + mf * 16 + r4;
                float2 o0, o1;
                o0.x = acc[mf][nf][0] + bx; o0.y = acc[mf][nf][1] + by;
                o1.x = acc[mf][nf][2] + bx; o1.y = acc[mf][nf][3] + by;
                *reinterpret_cast<float2*>(Om + (size_t)row0 * C_OUT + col) = o0;
                *reinterpret_cast<float2*>(Om + (size_t)(row0 + 8) * C_OUT + col) = o1;
                acc[mf][nf][0] = 0.0f; acc[mf][nf][1] = 0.0f;
                acc[mf][nf][2] = 0.0f; acc[mf][nf][3] = 0.0f;
            }
        }
    }
}

extern "C" void kernel_launch(void* const* d_in, const int* in_sizes, int n_in,
                              void* d_out, int out_size) {
    const float* x       = (const float*)d_in[0];
    const float* weight  = (const float*)d_in[1];
    const float* bias    = (const float*)d_in[2];
    const int*   indices = (const int*)d_in[3];
    const int*   t_ptr   = (n_in > 4) ? (const int*)d_in[4] : nullptr;
    float*       out     = (float*)d_out;

    {
        dim3 grid(C_OUT / 32, C_IN / 32, N_SEL);
        dim3 block(32, 8);
        wt_prep_kernel<<<grid, block>>>(weight, indices, t_ptr);
    }
    {
        cudaFuncSetAttribute(gemm_f16_kernel,
                             cudaFuncAttributeMaxDynamicSharedMemorySize, SM_TOTAL);
        dim3 grid(2, N_SEL);    // (m-half, n_sel) = 384 CTAs
        dim3 block(THREADS);
        gemm_f16_kernel<<<grid, block, SM_TOTAL>>>(x, bias, indices, t_ptr, out);
    }
}

// round 15
// speedup vs baseline: 1.4475x; 1.2767x over previous
#include <cuda_runtime.h>
#include <cuda_fp16.h>
#include <cstdint>

#define N_SEL   192
#define N_PTS   2048
#define C_IN    256
#define C_OUT   256
#define N_TILES 8

#define BM 64
#define BN 256
#define BK 32
#define NSLABS (C_IN / BK)   // 8
#define THREADS 256

#define ROWB   80            // tile row bytes: 32 fp16 (64B) + 16 pad

// dynamic smem layout
#define SM_BIAS  0                         // 256 f32 = 1024 B
#define SM_AH    1024                      // 2 stages x 64 rows x 80 B
#define A_STG    (BM * ROWB)               // 5120
#define SM_B     (SM_AH + 2 * A_STG)       // 11264; 4 stages x 256 rows x 80 B
#define B_STG    (BN * ROWB)               // 20480
#define SM_TOTAL (SM_B + 4 * B_STG)        // 93184

// gathered, transposed fp16 weights: [n_sel][N=C_OUT][K=C_IN]
__device__ __half g_wt[(size_t)N_SEL * C_OUT * C_IN];

__device__ __forceinline__ uint32_t smem_u32(const void* p) {
    uint32_t a;
    asm("{ .reg .u64 t; cvta.to.shared.u64 t, %1; cvt.u32.u64 %0, t; }" : "=r"(a) : "l"(p));
    return a;
}
__device__ __forceinline__ void cp16(uint32_t dst, const void* src) {
    asm volatile("cp.async.cg.shared.global [%0], [%1], 16;" :: "r"(dst), "l"(src));
}
__device__ __forceinline__ uint32_t pack_h2(float a, float b) {
    uint32_t r;
    asm("cvt.rn.f16x2.f32 %0, %2, %1;" : "=r"(r) : "f"(a), "f"(b));
    return r;
}
__device__ __forceinline__ void ldmx4(uint32_t addr, uint32_t& r0, uint32_t& r1,
                                      uint32_t& r2, uint32_t& r3) {
    asm volatile("ldmatrix.sync.aligned.m8n8.x4.shared.b16 {%0,%1,%2,%3}, [%4];"
                 : "=r"(r0), "=r"(r1), "=r"(r2), "=r"(r3) : "r"(addr));
}
__device__ __forceinline__ void mma_f16(float* c, const uint32_t* a, const uint32_t* b) {
    asm volatile("mma.sync.aligned.m16n8k16.row.col.f32.f16.f16.f32 "
                 "{%0,%1,%2,%3}, {%4,%5,%6,%7}, {%8,%9}, {%0,%1,%2,%3};"
                 : "+f"(c[0]), "+f"(c[1]), "+f"(c[2]), "+f"(c[3])
                 : "r"(a[0]), "r"(a[1]), "r"(a[2]), "r"(a[3]), "r"(b[0]), "r"(b[1]));
}

// ---------------- kernel 1: gather + transpose + fp16 convert of W ----------------
__global__ void wt_prep_kernel(const float* __restrict__ weight,
                               const int* __restrict__ indices,
                               const int* __restrict__ t_ptr) {
    const int n = blockIdx.z;
    const int t = (t_ptr != nullptr) ? *t_ptr : 3;
    const int idx = indices[n];
    const float* W = weight + (((size_t)idx * N_TILES + t) * C_IN) * C_OUT; // [K][N]

    __shared__ float tile[32][33];
    const int tx = threadIdx.x;   // 0..31
    const int ty = threadIdx.y;   // 0..7
    const int kt = blockIdx.y * 32;
    const int nt = blockIdx.x * 32;

    #pragma unroll
    for (int j = 0; j < 4; j++) {
        const int k = kt + ty + j * 8;
        tile[ty + j * 8][tx] = W[(size_t)k * C_OUT + nt + tx];
    }
    __syncthreads();

    __half* o = g_wt + (size_t)n * C_OUT * C_IN;
    #pragma unroll
    for (int j = 0; j < 4; j++) {
        const int nn = nt + ty + j * 8;
        o[(size_t)nn * C_IN + kt + tx] = __float2half_rn(tile[tx][ty + j * 8]);
    }
}

// ---------------- kernel 2: fp16 mma.sync GEMM, 4-deep B ring ----------------
__global__ __launch_bounds__(THREADS, 2)
void gemm_f16_kernel(const float* __restrict__ x,
                     const float* __restrict__ bias,
                     const int* __restrict__ indices,
                     const int* __restrict__ t_ptr,
                     float* __restrict__ out) {
    extern __shared__ __align__(16) unsigned char smem[];
    const uint32_t sa = smem_u32(smem);

    const int tid  = threadIdx.x;
    const int lane = tid & 31;
    const int wid  = tid >> 5;          // 0..7

    const int n_sel = blockIdx.y;
    const int m0    = blockIdx.x * BM;
    const int t   = (t_ptr != nullptr) ? *t_ptr : 3;
    const int idx = indices[n_sel];

    const float* A = x + (size_t)n_sel * N_PTS * C_IN + (size_t)m0 * C_IN;
    const __half* Wn = g_wt + (size_t)n_sel * C_OUT * C_IN;

    // bias -> smem
    float* bs = (float*)(smem + SM_BIAS);
    if (tid < C_OUT) bs[tid] = bias[((size_t)idx * N_TILES + t) * C_OUT + tid];

    // warp tiling: 2 m-warps x 4 n-warps; warp tile 32x64
    const int m_off = (wid >> 2) * 32;
    const int n_off = (wid & 3) * 64;

    float acc[2][8][4];
    #pragma unroll
    for (int i = 0; i < 2; i++)
        #pragma unroll
        for (int j = 0; j < 8; j++)
            #pragma unroll
            for (int q = 0; q < 4; q++)
                acc[i][j][q] = 0.0f;

    // per-thread A load mapping: 256 threads -> 64 rows x 32 cols (8 floats/thread)
    const int ar  = tid >> 2;            // row 0..63
    const int as8 = (tid & 3) * 8;       // col start (floats)

    // B cp.async mapping: 1024 chunks of 16B (256 rows x 4 chunks)
    auto issue_B = [&](int s) {
        const uint32_t base = sa + SM_B + (uint32_t)(s & 3) * B_STG;
        const int k0 = s * BK;
        #pragma unroll
        for (int i = 0; i < 4; i++) {
            const int c = tid + i * THREADS;
            const int r = c >> 2, seg = c & 3;
            cp16(base + (uint32_t)(r * ROWB + seg * 16),
                 Wn + (size_t)r * C_IN + k0 + seg * 8);
        }
        asm volatile("cp.async.commit_group;" ::: "memory");
    };

    // prologue: A slab 0 into regs, B slabs 0..2 in flight
    float4 a0, a1;
    {
        const float* src = A + (size_t)ar * C_IN + as8;
        a0 = *reinterpret_cast<const float4*>(src);
        a1 = *reinterpret_cast<const float4*>(src + 4);
    }
    issue_B(0);
    issue_B(1);
    issue_B(2);

    for (int s = 0; s < NSLABS; s++) {
        const int stgA = s & 1;

        // convert A regs (slab s) -> fp16 smem stage stgA
        // (stage last read in slab s-2; those reads complete before barrier s-1)
        {
            const uint32_t off = (uint32_t)(SM_AH + stgA * A_STG + ar * ROWB + (as8 >> 3) * 16);
            uint4 v;
            v.x = pack_h2(a0.x, a0.y);
            v.y = pack_h2(a0.z, a0.w);
            v.z = pack_h2(a1.x, a1.y);
            v.w = pack_h2(a1.z, a1.w);
            *reinterpret_cast<uint4*>(smem + off) = v;
        }

        // prefetch A slab s+1 into regs
        if (s + 1 < NSLABS) {
            const float* src = A + (size_t)ar * C_IN + (s + 1) * BK + as8;
            a0 = *reinterpret_cast<const float4*>(src);
            a1 = *reinterpret_cast<const float4*>(src + 4);
        }

        // B(s) was issued 3 slabs ago -> this wait should be a no-op
        const int rem = NSLABS - 1 - s;          // groups still wanted after B(s)
        if (rem >= 2)      asm volatile("cp.async.wait_group 2;" ::: "memory");
        else if (rem == 1) asm volatile("cp.async.wait_group 1;" ::: "memory");
        else               asm volatile("cp.async.wait_group 0;" ::: "memory");
        __syncthreads();   // A stage stgA + B stage s&3 ready; compute(s-1) done CTA-wide

        // refill ring: stage (s+3)&3 == (s-1)&3 was last read in slab s-1,
        // which the barrier above just retired -> safe to overwrite now.
        if (s + 3 < NSLABS) issue_B(s + 3);

        const uint32_t aB = sa + SM_AH + (uint32_t)(stgA * A_STG);
        const uint32_t bB = sa + SM_B  + (uint32_t)((s & 3) * B_STG);

        #pragma unroll
        for (int ks = 0; ks < BK; ks += 16) {
            uint32_t bf[8][2];
            #pragma unroll
            for (int p = 0; p < 4; p++) {
                const int quad = lane >> 3;
                const int rowB = n_off + p * 16 + ((quad >> 1) & 1) * 8 + (lane & 7);
                const int colB = ks + (quad & 1) * 8;
                ldmx4(bB + (uint32_t)(rowB * ROWB + colB * 2),
                      bf[2 * p][0], bf[2 * p][1], bf[2 * p + 1][0], bf[2 * p + 1][1]);
            }
            #pragma unroll
            for (int mf = 0; mf < 2; mf++) {
                const int rowA = m_off + mf * 16 + (lane & 15);
                const int colA = ks + ((lane >> 4) & 1) * 8;
                uint32_t af[4];
                ldmx4(aB + (uint32_t)(rowA * ROWB + colA * 2), af[0], af[1], af[2], af[3]);
                #pragma unroll
                for (int nf = 0; nf < 8; nf++)
                    mma_f16(acc[mf][nf], af, bf[nf]);
            }
        }
    }

    // ---- epilogue: + bias, float2 stores ----
    float* Out = out + (size_t)n_sel * N_PTS * C_OUT + (size_t)m0 * C_OUT;
    const int r4 = lane >> 2;
    const int c2 = (lane & 3) * 2;
    #pragma unroll
    for (int mf = 0; mf < 2; mf++) {
        #pragma unroll
        for (int nf = 0; nf < 8; nf++) {
            const int col = n_off + nf * 8 + c2;
            const float bx = bs[col], by = bs[col + 1];
            const int row0 = m_off + mf * 16 + r4;
            float2 o0, o1;
            o0.x = acc[mf][nf][0] + bx; o0.y = acc[mf][nf][1] + by;
            o1.x = acc[mf][nf][2] + bx; o1.y = acc[mf][nf][3] + by;
            *reinterpret_cast<float2*>(Out + (size_t)row0 * C_OUT + col) = o0;
            *reinterpret_cast<float2*>(Out + (size_t)(row0 + 8) * C_OUT + col) = o1;
        }
    }
}

extern "C" void kernel_launch(void* const* d_in, const int* in_sizes, int n_in,
                              void* d_out, int out_size) {
    const float* x       = (const float*)d_in[0];
    const float* weight  = (const float*)d_in[1];
    const float* bias    = (const float*)d_in[2];
    const int*   indices = (const int*)d_in[3];
    const int*   t_ptr   = (n_in > 4) ? (const int*)d_in[4] : nullptr;
    float*       out     = (float*)d_out;

    {
        dim3 grid(C_OUT / 32, C_IN / 32, N_SEL);
        dim3 block(32, 8);
        wt_prep_kernel<<<grid, block>>>(weight, indices, t_ptr);
    }
    {
        cudaFuncSetAttribute(gemm_f16_kernel,
                             cudaFuncAttributeMaxDynamicSharedMemorySize, SM_TOTAL);
        dim3 grid(N_PTS / BM, N_SEL);   // (32, 192); m fastest -> same-W adjacency
        dim3 block(THREADS);
        gemm_f16_kernel<<<grid, block, SM_TOTAL>>>(x, bias, indices, t_ptr, out);
    }
}

// round 16
// speedup vs baseline: 1.4807x; 1.0229x over previous
#include <cuda_runtime.h>
#include <cuda_fp16.h>
#include <cstdint>

#define N_SEL   192
#define N_PTS   2048
#define C_IN    256
#define C_OUT   256
#define N_TILES 8

#define BM 64
#define BN 256
#define BK 32
#define NSLABS (C_IN / BK)   // 8
#define THREADS 256

#define ROWA   80            // A tile row: 32 fp16 (64B) + 16 pad
#define ROWBK  528           // B tile row ([K][N]): 256 fp16 (512B) + 16 pad; 33x16B, %8=1

// dynamic smem layout
#define SM_BIAS  0                         // 256 f32 = 1024 B
#define SM_AH    1024                      // 2 stages x 64 rows x 80 B
#define A_STG    (BM * ROWA)               // 5120
#define SM_B     (SM_AH + 2 * A_STG)       // 11264; 4 stages x 32 k-rows x 528 B
#define B_STG    (BK * ROWBK)              // 16896
#define SM_TOTAL (SM_B + 4 * B_STG)        // 78848

// gathered fp16 weights, ORIGINAL [K][N] order: [n_sel][K=C_IN][N=C_OUT]
__device__ __half g_wt[(size_t)N_SEL * C_IN * C_OUT];

__device__ __forceinline__ uint32_t smem_u32(const void* p) {
    uint32_t a;
    asm("{ .reg .u64 t; cvta.to.shared.u64 t, %1; cvt.u32.u64 %0, t; }" : "=r"(a) : "l"(p));
    return a;
}
__device__ __forceinline__ void cp16(uint32_t dst, const void* src) {
    asm volatile("cp.async.cg.shared.global [%0], [%1], 16;" :: "r"(dst), "l"(src));
}
__device__ __forceinline__ uint32_t pack_h2(float a, float b) {
    uint32_t r;
    asm("cvt.rn.f16x2.f32 %0, %2, %1;" : "=r"(r) : "f"(a), "f"(b));
    return r;
}
__device__ __forceinline__ void ldmx4(uint32_t addr, uint32_t& r0, uint32_t& r1,
                                      uint32_t& r2, uint32_t& r3) {
    asm volatile("ldmatrix.sync.aligned.m8n8.x4.shared.b16 {%0,%1,%2,%3}, [%4];"
                 : "=r"(r0), "=r"(r1), "=r"(r2), "=r"(r3) : "r"(addr));
}
__device__ __forceinline__ void ldmx4t(uint32_t addr, uint32_t& r0, uint32_t& r1,
                                       uint32_t& r2, uint32_t& r3) {
    asm volatile("ldmatrix.sync.aligned.m8n8.x4.trans.shared.b16 {%0,%1,%2,%3}, [%4];"
                 : "=r"(r0), "=r"(r1), "=r"(r2), "=r"(r3) : "r"(addr));
}
__device__ __forceinline__ void mma_f16(float* c, const uint32_t* a, const uint32_t* b) {
    asm volatile("mma.sync.aligned.m16n8k16.row.col.f32.f16.f16.f32 "
                 "{%0,%1,%2,%3}, {%4,%5,%6,%7}, {%8,%9}, {%0,%1,%2,%3};"
                 : "+f"(c[0]), "+f"(c[1]), "+f"(c[2]), "+f"(c[3])
                 : "r"(a[0]), "r"(a[1]), "r"(a[2]), "r"(a[3]), "r"(b[0]), "r"(b[1]));
}

// ---------------- kernel 1: gather + fp16 convert of W (NO transpose) ----------------
// Each block converts 8192 consecutive floats of one selected W matrix.
__global__ void wt_prep_kernel(const float* __restrict__ weight,
                               const int* __restrict__ indices,
                               const int* __restrict__ t_ptr) {
    const int n = blockIdx.y;
    const int t = (t_ptr != nullptr) ? *t_ptr : 3;
    const int idx = indices[n];
    const float* W = weight + (((size_t)idx * N_TILES + t) * C_IN) * C_OUT;
    __half* o = g_wt + (size_t)n * C_IN * C_OUT;

    const int base4 = blockIdx.x * 2048;     // in float4 units (8192 floats / block)
    #pragma unroll
    for (int j = 0; j < 8; j++) {
        const int g = base4 + threadIdx.x + j * 256;          // float4 index
        const float4 f = reinterpret_cast<const float4*>(W)[g];
        uint2 v;
        v.x = pack_h2(f.x, f.y);
        v.y = pack_h2(f.z, f.w);
        reinterpret_cast<uint2*>(o)[g] = v;
    }
}

// ---------------- kernel 2: fp16 mma.sync GEMM, 4-deep B ring, trans-B ----------------
__global__ __launch_bounds__(THREADS, 2)
void gemm_f16_kernel(const float* __restrict__ x,
                     const float* __restrict__ bias,
                     const int* __restrict__ indices,
                     const int* __restrict__ t_ptr,
                     float* __restrict__ out) {
    extern __shared__ __align__(16) unsigned char smem[];
    const uint32_t sa = smem_u32(smem);

    const int tid  = threadIdx.x;
    const int lane = tid & 31;
    const int wid  = tid >> 5;          // 0..7

    const int n_sel = blockIdx.y;
    const int m0    = blockIdx.x * BM;
    const int t   = (t_ptr != nullptr) ? *t_ptr : 3;
    const int idx = indices[n_sel];

    const float* A = x + (size_t)n_sel * N_PTS * C_IN + (size_t)m0 * C_IN;
    const __half* Wn = g_wt + (size_t)n_sel * C_IN * C_OUT;   // [K][N]

    // B cp.async: slab = 32 k-rows x 512B = 1024 x 16B chunks, 4/thread
    auto issue_B = [&](int s) {
        const uint32_t base = sa + SM_B + (uint32_t)(s & 3) * B_STG;
        const int k0 = s * BK;
        #pragma unroll
        for (int i = 0; i < 4; i++) {
            const int c = tid + i * THREADS;     // 0..1023
            const int r = c >> 5, seg = c & 31;  // k-row, 16B segment
            cp16(base + (uint32_t)(r * ROWBK + seg * 16),
                 Wn + (size_t)(k0 + r) * C_OUT + seg * 8);
        }
        asm volatile("cp.async.commit_group;" ::: "memory");
    };

    // B first: get DRAM/L2 requests flying earliest
    issue_B(0);
    issue_B(1);
    issue_B(2);

    // bias -> smem (THREADS == C_OUT)
    float* bs = (float*)(smem + SM_BIAS);
    bs[tid] = bias[((size_t)idx * N_TILES + t) * C_OUT + tid];

    // warp tiling: 2 m-warps x 4 n-warps; warp tile 32x64
    const int m_off = (wid >> 2) * 32;
    const int n_off = (wid & 3) * 64;

    float acc[2][8][4];
    #pragma unroll
    for (int i = 0; i < 2; i++)
        #pragma unroll
        for (int j = 0; j < 8; j++)
            #pragma unroll
            for (int q = 0; q < 4; q++)
                acc[i][j][q] = 0.0f;

    // per-thread A load mapping: 256 threads -> 64 rows x 32 cols (8 floats/thread)
    const int ar  = tid >> 2;            // row 0..63
    const int as8 = (tid & 3) * 8;       // col start (floats)

    // prologue A slab 0
    float4 a0, a1;
    {
        const float* src = A + (size_t)ar * C_IN + as8;
        a0 = *reinterpret_cast<const float4*>(src);
        a1 = *reinterpret_cast<const float4*>(src + 4);
    }

    // precomputed lane geometry for trans-B ldmatrix
    const int bq      = lane >> 3;                 // octet 0..3
    const int bk_lane = (bq & 1) * 8 + (lane & 7); // k-row within 16-k span
    const int bn_oct  = ((bq >> 1) & 1) * 8;       // n-octet offset

    for (int s = 0; s < NSLABS; s++) {
        const int stgA = s & 1;

        // convert A regs (slab s) -> fp16 smem stage stgA
        {
            const uint32_t off = (uint32_t)(SM_AH + stgA * A_STG + ar * ROWA + (as8 >> 3) * 16);
            uint4 v;
            v.x = pack_h2(a0.x, a0.y);
            v.y = pack_h2(a0.z, a0.w);
            v.z = pack_h2(a1.x, a1.y);
            v.w = pack_h2(a1.z, a1.w);
            *reinterpret_cast<uint4*>(smem + off) = v;
        }

        // prefetch A slab s+1 into regs
        if (s + 1 < NSLABS) {
            const float* src = A + (size_t)ar * C_IN + (s + 1) * BK + as8;
            a0 = *reinterpret_cast<const float4*>(src);
            a1 = *reinterpret_cast<const float4*>(src + 4);
        }

        // B(s) was issued 3 slabs ago -> wait should be a no-op
        const int rem = NSLABS - 1 - s;
        if (rem >= 2)      asm volatile("cp.async.wait_group 2;" ::: "memory");
        else if (rem == 1) asm volatile("cp.async.wait_group 1;" ::: "memory");
        else               asm volatile("cp.async.wait_group 0;" ::: "memory");
        __syncthreads();   // A stage stgA + B stage s&3 ready; compute(s-1) retired

        // refill ring: stage (s+3)&3 == (s-1)&3 last read in slab s-1 (retired above)
        if (s + 3 < NSLABS) issue_B(s + 3);

        const uint32_t aB = sa + SM_AH + (uint32_t)(stgA * A_STG);
        const uint32_t bB = sa + SM_B  + (uint32_t)((s & 3) * B_STG);

        #pragma unroll
        for (int ks = 0; ks < BK; ks += 16) {
            uint32_t bf[8][2];
            #pragma unroll
            for (int p = 0; p < 4; p++) {
                // x4.trans on [K][N]: octet q -> tile (k-oct q&1, n-oct q>>1);
                // output reg q = transposed tile = col-major fragment
                const int krow = ks + bk_lane;
                const int ncol = n_off + p * 16 + bn_oct;
                ldmx4t(bB + (uint32_t)(krow * ROWBK + ncol * 2),
                       bf[2 * p][0], bf[2 * p][1], bf[2 * p + 1][0], bf[2 * p + 1][1]);
            }
            #pragma unroll
            for (int mf = 0; mf < 2; mf++) {
                const int rowA = m_off + mf * 16 + (lane & 15);
                const int colA = ks + ((lane >> 4) & 1) * 8;
                uint32_t af[4];
                ldmx4(aB + (uint32_t)(rowA * ROWA + colA * 2), af[0], af[1], af[2], af[3]);
                #pragma unroll
                for (int nf = 0; nf < 8; nf++)
                    mma_f16(acc[mf][nf], af, bf[nf]);
            }
        }
    }

    // ---- epilogue: + bias, float2 stores ----
    float* Out = out + (size_t)n_sel * N_PTS * C_OUT + (size_t)m0 * C_OUT;
    const int r4 = lane >> 2;
    const int c2 = (lane & 3) * 2;
    #pragma unroll
    for (int mf = 0; mf < 2; mf++) {
        #pragma unroll
        for (int nf = 0; nf < 8; nf++) {
            const int col = n_off + nf * 8 + c2;
            const float bx = bs[col], by = bs[col + 1];
            const int row0 = m_off + mf * 16 + r4;
            float2 o0, o1;
            o0.x = acc[mf][nf][0] + bx; o0.y = acc[mf][nf][1] + by;
            o1.x = acc[mf][nf][2] + bx; o1.y = acc[mf][nf][3] + by;
            *reinterpret_cast<float2*>(Out + (size_t)row0 * C_OUT + col) = o0;
            *reinterpret_cast<float2*>(Out + (size_t)(row0 + 8) * C_OUT + col) = o1;
        }
    }
}

extern "C" void kernel_launch(void* const* d_in, const int* in_sizes, int n_in,
                              void* d_out, int out_size) {
    const float* x       = (const float*)d_in[0];
    const float* weight  = (const float*)d_in[1];
    const float* bias    = (const float*)d_in[2];
    const int*   indices = (const int*)d_in[3];
    const int*   t_ptr   = (n_in > 4) ? (const int*)d_in[4] : nullptr;
    float*       out     = (float*)d_out;

    {
        dim3 grid(8, N_SEL);     // 8 blocks x 8192 floats = 64K elems per n_sel
        dim3 block(THREADS);
        wt_prep_kernel<<<grid, block>>>(weight, indices, t_ptr);
    }
    {
        cudaFuncSetAttribute(gemm_f16_kernel,
                             cudaFuncAttributeMaxDynamicSharedMemorySize, SM_TOTAL);
        dim3 grid(N_PTS / BM, N_SEL);   // (32, 192); m fastest -> same-W adjacency
        dim3 block(THREADS);
        gemm_f16_kernel<<<grid, block, SM_TOTAL>>>(x, bias, indices, t_ptr, out);
    }
}